// round 5
// baseline (speedup 1.0000x reference)
#include <cuda_runtime.h>
#include <stdint.h>

#define NCAND  1600
#define NITER  100
#define NZ     16
#define NB     524288
#define CHUNK  1024
#define NCHUNK (NB / CHUNK)     // 512
#define MMGRID 512

#define CNT_SHIFT 42
#define SUM_MASK  ((1ull << 42) - 1ull)
#define BIAS      (1 << 20)
#define FIXS_F    68719476736.0f          // 2^36 (exact in f32)
#define INVFIXS   (1.0 / 68719476736.0)

typedef unsigned long long u64;
typedef long long          s64;
typedef unsigned           u32;

// ---------------- device scratch ----------------
__device__ float  g_bmin[MMGRID];
__device__ float  g_bmax[MMGRID];
__device__ float  g_xminf, g_xmaxf, g_invwf;
__device__ s64    g_cmin, g_W36;
__device__ float  g_sc[NCAND];
__device__ float  g_ql[NCAND];
__device__ float  g_newmin[NCAND];
__device__ float  g_newmax[NCAND];
__device__ u64    g_hist[NB];
__device__ u32    g_pc[NB + 1];
__device__ u64    g_ps[NB + 1];
__device__ u32    g_ccnt[NCHUNK];
__device__ u64    g_csum[NCHUNK];

// ---------------- pass A: min/max per block + clear histogram ----------------
__global__ void minmax_clear_kernel(const float4* __restrict__ x4, int n4) {
    int stride = gridDim.x * blockDim.x;
    int tid0 = blockIdx.x * blockDim.x + threadIdx.x;

    // clear the packed histogram (4 MB)
    for (int i = tid0; i < NB; i += stride) g_hist[i] = 0ull;

    float lmin = 3.4e38f, lmax = -3.4e38f;
    for (int i = tid0; i < n4; i += stride) {
        float4 v = x4[i];
        lmin = fminf(lmin, fminf(fminf(v.x, v.y), fminf(v.z, v.w)));
        lmax = fmaxf(lmax, fmaxf(fmaxf(v.x, v.y), fmaxf(v.z, v.w)));
    }
    #pragma unroll
    for (int o = 16; o; o >>= 1) {
        lmin = fminf(lmin, __shfl_xor_sync(0xffffffffu, lmin, o));
        lmax = fmaxf(lmax, __shfl_xor_sync(0xffffffffu, lmax, o));
    }
    __shared__ float smin[8], smax[8];
    int w = threadIdx.x >> 5;
    if ((threadIdx.x & 31) == 0) { smin[w] = lmin; smax[w] = lmax; }
    __syncthreads();
    if (threadIdx.x == 0) {
        for (int i = 1; i < (int)(blockDim.x >> 5); i++) {
            lmin = fminf(lmin, smin[i]);
            lmax = fmaxf(lmax, smax[i]);
        }
        g_bmin[blockIdx.x] = lmin;
        g_bmax[blockIdx.x] = lmax;
    }
}

// ---------------- pass B: finish min/max + candidate params -------------------
__global__ void __launch_bounds__(512) cand_kernel() {
    __shared__ float smn[512], smx[512];
    int t = threadIdx.x;
    smn[t] = g_bmin[t];              // MMGRID == 512
    smx[t] = g_bmax[t];
    __syncthreads();
    for (int off = 256; off; off >>= 1) {
        if (t < off) {
            smn[t] = fminf(smn[t], smn[t + off]);
            smx[t] = fmaxf(smx[t], smx[t + off]);
        }
        __syncthreads();
    }
    const float x_min = smn[0];
    const float x_max = smx[0];
    const float xrange = x_max - x_min;
    if (t == 0) {
        g_xminf = x_min;
        g_xmaxf = x_max;
        g_invwf = (float)NB / xrange;
        float wbin = xrange / (float)NB;
        g_W36  = llrintf(wbin * FIXS_F);
        g_cmin = llrintf(x_min * FIXS_F);
    }
    const float EPS = 1.1920929e-7f;
    for (int c = t; c < NCAND; c += 512) {
        int i = c / NZ + 1;
        int z = c % NZ;
        float fi = (float)i, fz = (float)z;
        float tmp_max   = xrange / 100.0f * fi;
        float tmp_delta = tmp_max / 15.0f;
        float new_min = fmaxf(-fz * tmp_delta, x_min);
        float new_max = fminf(tmp_max - fz * tmp_delta, x_max);
        float min_neg = fminf(new_min, 0.0f);
        float max_pos = fmaxf(new_max, 0.0f);
        float scale = fmaxf((max_pos - min_neg) / 15.0f, EPS);
        float zp = fminf(fmaxf(0.0f - rintf(min_neg / scale), 0.0f), 15.0f);
        g_sc[c] = scale;
        g_ql[c] = -zp;
        g_newmin[c] = new_min;
        g_newmax[c] = new_max;
    }
}

// ---------------- pass C: histogram, ONE u64 atomic per element ---------------
// packed per element: (1<<42) | (fx - b*W36 + BIAS)
//   fx = llrintf(x*2^36) - llrintf(xmin*2^36)   (exact to ~1.5*2^-36)
// reconstruction adds cnt*(b*W36 - BIAS) back -> exact integer inverse.
__global__ void hist_kernel(const float4* __restrict__ x4, int n4) {
    const float xminf = g_xminf;
    const float invwf = g_invwf;
    const s64   cmin  = g_cmin;
    const s64   W36   = g_W36;
    for (int i = blockIdx.x * blockDim.x + threadIdx.x; i < n4;
         i += gridDim.x * blockDim.x) {
        float4 v = x4[i];
        float f[4] = {v.x, v.y, v.z, v.w};
        #pragma unroll
        for (int k = 0; k < 4; k++) {
            float d = f[k] - xminf;
            int b = (int)(d * invwf);
            b = min(max(b, 0), NB - 1);
            s64 fx = llrintf(f[k] * FIXS_F) - cmin;
            u64 val = (1ull << CNT_SHIFT) +
                      (u64)(fx - (s64)b * W36 + (s64)BIAS);
            atomicAdd(&g_hist[b], val);
        }
    }
}

// ---------------- pass D1: per-chunk totals (count, adjusted fx-sum) ----------
__global__ void chunkred_kernel() {
    __shared__ u32 sc[256];
    __shared__ u64 ss[256];
    int b = blockIdx.x, t = threadIdx.x;
    const s64 W36 = g_W36;
    u32 c = 0; u64 s = 0;
    for (int j = t; j < CHUNK; j += 256) {
        int bin = b * CHUNK + j;
        u64 p = g_hist[bin];
        u32 cnt = (u32)(p >> CNT_SHIFT);
        s64 adj = (s64)(p & SUM_MASK) + (s64)cnt * ((s64)bin * W36 - (s64)BIAS);
        c += cnt; s += (u64)adj;
    }
    sc[t] = c; ss[t] = s; __syncthreads();
    for (int off = 128; off; off >>= 1) {
        if (t < off) { sc[t] += sc[t + off]; ss[t] += ss[t + off]; }
        __syncthreads();
    }
    if (t == 0) { g_ccnt[b] = sc[0]; g_csum[b] = ss[0]; }
}

// ---------------- pass D2: within-chunk scan (chunk offset computed inline) ---
__global__ void __launch_bounds__(CHUNK) binscan_kernel() {
    __shared__ u32 sc[CHUNK];
    __shared__ u64 ss[CHUNK];
    int b = blockIdx.x, t = threadIdx.x;
    const s64 W36 = g_W36;

    // exclusive offset = sum of chunk totals for chunks < b (block reduction)
    u32 co = 0; u64 so = 0;
    for (int j = t; j < b; j += CHUNK) { co += g_ccnt[j]; so += g_csum[j]; }
    sc[t] = co; ss[t] = so; __syncthreads();
    for (int off = 512; off; off >>= 1) {
        if (t < off) { sc[t] += sc[t + off]; ss[t] += ss[t + off]; }
        __syncthreads();
    }
    co = sc[0]; so = ss[0];
    __syncthreads();

    int i = b * CHUNK + t;
    u64 p = g_hist[i];
    u32 v = (u32)(p >> CNT_SHIFT);
    s64 adj = (s64)(p & SUM_MASK) + (s64)v * ((s64)i * W36 - (s64)BIAS);
    u64 w = (u64)adj;
    sc[t] = v; ss[t] = w; __syncthreads();
    for (int off = 1; off < CHUNK; off <<= 1) {
        u32 a = 0; u64 a2 = 0;
        if (t >= off) { a = sc[t - off]; a2 = ss[t - off]; }
        __syncthreads();
        sc[t] += a; ss[t] += a2;
        __syncthreads();
    }
    g_pc[i] = co + (sc[t] - v);
    g_ps[i] = so + (ss[t] - w);
    if (i == NB - 1) {
        g_pc[NB] = co + sc[t];
        g_ps[NB] = so + ss[t];
    }
}

// ---------------- pass E: scores + reference-exact argmin, fused --------------
__device__ __forceinline__ int gidx(float E, float xminf, float invwf) {
    float t = (E - xminf) * invwf;
    if (!(t > 0.0f)) return 0;
    if (t >= (float)NB) return NB;
    return (int)t;
}

__global__ void __launch_bounds__(1024) finish_kernel(float* __restrict__ out,
                                                      int ntot) {
    __shared__ double s_score[NCAND];
    __shared__ double sm_i[NITER];
    __shared__ int    j_i[NITER];
    int t = threadIdx.x;
    const float xminf = g_xminf;
    const float invwf = g_invwf;
    const double cmind = (double)g_cmin;

    for (int c = t; c < NCAND; c += 1024) {
        float s  = g_sc[c];
        float ql = g_ql[c];
        int e[NZ + 1];
        e[0] = 0; e[NZ] = NB;
        #pragma unroll
        for (int m = 0; m < NZ - 1; m++)
            e[m + 1] = gidx((ql + (float)m + 0.5f) * s, xminf, invwf);
        #pragma unroll
        for (int m = 1; m < NZ; m++) if (e[m] < e[m - 1]) e[m] = e[m - 1];
        double num = 0.0;
        #pragma unroll
        for (int m = 0; m < NZ; m++) {
            u32 pc0 = g_pc[e[m]], pc1 = g_pc[e[m + 1]];
            u64 ps0 = g_ps[e[m]], ps1 = g_ps[e[m + 1]];
            double Nm = (double)(pc1 - pc0);
            double S1 = ((double)(s64)(ps1 - ps0) + Nm * cmind) * INVFIXS;
            float a = (ql + (float)m) * s;
            double ad = (double)a;
            num += ad * ad * Nm - 2.0 * ad * S1;
        }
        s_score[c] = num / (double)ntot;   // S2tot omitted: constant offset
    }
    __syncthreads();

    if (t < NITER) {
        int j = 0;
        double sm = s_score[t * NZ];
        #pragma unroll
        for (int z = 1; z < NZ; z++) {
            double s = s_score[t * NZ + z];
            if (s < sm) { sm = s; j = z; }   // first-occurrence argmin
        }
        sm_i[t] = sm; j_i[t] = j;
    }
    __syncthreads();
    if (t == 0) {
        double best = 1e30;
        float bmin = g_xminf;
        float bmax = g_xmaxf;
        for (int i = 0; i < NITER; i++) {
            if (sm_i[i] < best) {             // strict <, like reference
                best = sm_i[i];
                bmin = g_newmin[i * NZ + j_i[i]];
                bmax = g_newmax[i * NZ + j_i[i]];
            }
        }
        out[0] = bmin;
        out[1] = bmax;
    }
}

extern "C" void kernel_launch(void* const* d_in, const int* in_sizes, int n_in,
                              void* d_out, int out_size) {
    const float* x = (const float*)d_in[0];
    int n = in_sizes[0];
    int n4 = n / 4;

    minmax_clear_kernel<<<MMGRID, 256>>>((const float4*)x, n4);
    cand_kernel<<<1, 512>>>();
    hist_kernel<<<2048, 256>>>((const float4*)x, n4);
    chunkred_kernel<<<NCHUNK, 256>>>();
    binscan_kernel<<<NCHUNK, CHUNK>>>();
    finish_kernel<<<1, 1024>>>((float*)d_out, n);
}

// round 6
// speedup vs baseline: 1.0163x; 1.0163x over previous
#include <cuda_runtime.h>
#include <stdint.h>

#define NCAND  1600
#define NITER  100
#define NZ     16
#define NB     131072                 // 2^17 bins
#define CHUNK  1024
#define NCHUNK (NB / CHUNK)           // 128
#define MMGRID 512

#define CNT_SHIFT 40
#define SUM_MASK  ((1ull << CNT_SHIFT) - 1ull)
#define BIAS      (1 << 21)
#define FIXS_F    68719476736.0f      // 2^36 (exact in f32)
#define INVFIXS   (1.0 / 68719476736.0)

typedef unsigned long long u64;
typedef long long          s64;
typedef unsigned           u32;

// ---------------- device scratch ----------------
__device__ float  g_bmin[MMGRID];
__device__ float  g_bmax[MMGRID];
__device__ float  g_xminf, g_xmaxf, g_invwf;
__device__ s64    g_cmin, g_W36;
__device__ float  g_sc[NCAND];
__device__ float  g_ql[NCAND];
__device__ float  g_newmin[NCAND];
__device__ float  g_newmax[NCAND];
__device__ u64    g_hist[NB];
__device__ u32    g_pc[NB + 1];
__device__ u64    g_ps[NB + 1];
__device__ u32    g_ccnt[NCHUNK];
__device__ u64    g_csum[NCHUNK];

// ---------------- pass A: per-block min/max + clear histogram ----------------
__global__ void minmax_clear_kernel(const float4* __restrict__ x4, int n4) {
    int stride = gridDim.x * blockDim.x;
    int tid0 = blockIdx.x * blockDim.x + threadIdx.x;

    for (int i = tid0; i < NB; i += stride) g_hist[i] = 0ull;   // 1 MB clear

    float lmin = 3.4e38f, lmax = -3.4e38f;
    for (int i = tid0; i < n4; i += stride) {
        float4 v = x4[i];
        lmin = fminf(lmin, fminf(fminf(v.x, v.y), fminf(v.z, v.w)));
        lmax = fmaxf(lmax, fmaxf(fmaxf(v.x, v.y), fmaxf(v.z, v.w)));
    }
    #pragma unroll
    for (int o = 16; o; o >>= 1) {
        lmin = fminf(lmin, __shfl_xor_sync(0xffffffffu, lmin, o));
        lmax = fmaxf(lmax, __shfl_xor_sync(0xffffffffu, lmax, o));
    }
    __shared__ float smin[8], smax[8];
    int w = threadIdx.x >> 5;
    if ((threadIdx.x & 31) == 0) { smin[w] = lmin; smax[w] = lmax; }
    __syncthreads();
    if (threadIdx.x == 0) {
        for (int i = 1; i < (int)(blockDim.x >> 5); i++) {
            lmin = fminf(lmin, smin[i]);
            lmax = fmaxf(lmax, smax[i]);
        }
        g_bmin[blockIdx.x] = lmin;
        g_bmax[blockIdx.x] = lmax;
    }
}

// ---------------- pass B: finish min/max + candidate params -------------------
__global__ void __launch_bounds__(512) cand_kernel() {
    __shared__ float smn[512], smx[512];
    int t = threadIdx.x;
    smn[t] = g_bmin[t];              // MMGRID == 512
    smx[t] = g_bmax[t];
    __syncthreads();
    for (int off = 256; off; off >>= 1) {
        if (t < off) {
            smn[t] = fminf(smn[t], smn[t + off]);
            smx[t] = fmaxf(smx[t], smx[t + off]);
        }
        __syncthreads();
    }
    const float x_min = smn[0];
    const float x_max = smx[0];
    const float xrange = x_max - x_min;
    if (t == 0) {
        g_xminf = x_min;
        g_xmaxf = x_max;
        g_invwf = (float)NB / xrange;
        float wbin = xrange / (float)NB;
        g_W36  = llrintf(wbin * FIXS_F);
        g_cmin = llrintf(x_min * FIXS_F);
    }
    const float EPS = 1.1920929e-7f;
    for (int c = t; c < NCAND; c += 512) {
        int i = c / NZ + 1;
        int z = c % NZ;
        float fi = (float)i, fz = (float)z;
        float tmp_max   = xrange / 100.0f * fi;
        float tmp_delta = tmp_max / 15.0f;
        float new_min = fmaxf(-fz * tmp_delta, x_min);
        float new_max = fminf(tmp_max - fz * tmp_delta, x_max);
        float min_neg = fminf(new_min, 0.0f);
        float max_pos = fmaxf(new_max, 0.0f);
        float scale = fmaxf((max_pos - min_neg) / 15.0f, EPS);
        float zp = fminf(fmaxf(0.0f - rintf(min_neg / scale), 0.0f), 15.0f);
        g_sc[c] = scale;
        g_ql[c] = -zp;
        g_newmin[c] = new_min;
        g_newmax[c] = new_max;
    }
}

// ---------------- pass C: histogram, ONE u64 atomic per element ---------------
// packed: (1<<40)*count | (fx - b*W36 + BIAS), fx = llrintf(x*2^36) - cmin.
// Reconstruction adds cnt*(b*W36 - BIAS) back -> exact integer inverse.
__global__ void hist_kernel(const float4* __restrict__ x4, int n4) {
    const float xminf = g_xminf;
    const float invwf = g_invwf;
    const s64   cmin  = g_cmin;
    const s64   W36   = g_W36;
    for (int i = blockIdx.x * blockDim.x + threadIdx.x; i < n4;
         i += gridDim.x * blockDim.x) {
        float4 v = x4[i];
        float f[4] = {v.x, v.y, v.z, v.w};
        #pragma unroll
        for (int k = 0; k < 4; k++) {
            float d = f[k] - xminf;
            int b = (int)(d * invwf);
            b = min(max(b, 0), NB - 1);
            s64 fx = llrintf(f[k] * FIXS_F) - cmin;
            u64 val = (1ull << CNT_SHIFT) +
                      (u64)(fx - (s64)b * W36 + (s64)BIAS);
            atomicAdd(&g_hist[b], val);
        }
    }
}

// ---------------- pass D1: per-chunk totals ----------------
__global__ void chunkred_kernel() {
    __shared__ u32 sc[256];
    __shared__ u64 ss[256];
    int b = blockIdx.x, t = threadIdx.x;
    const s64 W36 = g_W36;
    u32 c = 0; u64 s = 0;
    for (int j = t; j < CHUNK; j += 256) {
        int bin = b * CHUNK + j;
        u64 p = g_hist[bin];
        u32 cnt = (u32)(p >> CNT_SHIFT);
        s64 adj = (s64)(p & SUM_MASK) + (s64)cnt * ((s64)bin * W36 - (s64)BIAS);
        c += cnt; s += (u64)adj;
    }
    sc[t] = c; ss[t] = s; __syncthreads();
    for (int off = 128; off; off >>= 1) {
        if (t < off) { sc[t] += sc[t + off]; ss[t] += ss[t + off]; }
        __syncthreads();
    }
    if (t == 0) { g_ccnt[b] = sc[0]; g_csum[b] = ss[0]; }
}

// ---------------- pass D2: within-chunk scan (+inline chunk offsets) ----------
__global__ void __launch_bounds__(CHUNK) binscan_kernel() {
    __shared__ u32 sc[CHUNK];
    __shared__ u64 ss[CHUNK];
    int b = blockIdx.x, t = threadIdx.x;
    const s64 W36 = g_W36;

    u32 co = (t < b) ? g_ccnt[t] : 0u;     // b < NCHUNK=128 <= CHUNK threads
    u64 so = (t < b) ? g_csum[t] : 0ull;
    sc[t] = co; ss[t] = so; __syncthreads();
    for (int off = 512; off; off >>= 1) {
        if (t < off) { sc[t] += sc[t + off]; ss[t] += ss[t + off]; }
        __syncthreads();
    }
    co = sc[0]; so = ss[0];
    __syncthreads();

    int i = b * CHUNK + t;
    u64 p = g_hist[i];
    u32 v = (u32)(p >> CNT_SHIFT);
    s64 adj = (s64)(p & SUM_MASK) + (s64)v * ((s64)i * W36 - (s64)BIAS);
    u64 w = (u64)adj;
    sc[t] = v; ss[t] = w; __syncthreads();
    for (int off = 1; off < CHUNK; off <<= 1) {
        u32 a = 0; u64 a2 = 0;
        if (t >= off) { a = sc[t - off]; a2 = ss[t - off]; }
        __syncthreads();
        sc[t] += a; ss[t] += a2;
        __syncthreads();
    }
    g_pc[i] = co + (sc[t] - v);
    g_ps[i] = so + (ss[t] - w);
    if (i == NB - 1) {
        g_pc[NB] = co + sc[t];
        g_ps[NB] = so + ss[t];
    }
}

// ---------------- pass E: scores + reference-exact argmin, fused --------------
__device__ __forceinline__ int gidx(float E, float xminf, float invwf) {
    float t = (E - xminf) * invwf;
    if (!(t > 0.0f)) return 0;
    if (t >= (float)NB) return NB;
    return (int)t;
}

__global__ void __launch_bounds__(1024) finish_kernel(float* __restrict__ out,
                                                      int ntot) {
    __shared__ double s_score[NCAND];
    __shared__ double sm_i[NITER];
    __shared__ int    j_i[NITER];
    int t = threadIdx.x;
    const float xminf = g_xminf;
    const float invwf = g_invwf;
    const double cmind = (double)g_cmin;

    for (int c = t; c < NCAND; c += 1024) {
        float s  = g_sc[c];
        float ql = g_ql[c];
        int e[NZ + 1];
        e[0] = 0; e[NZ] = NB;
        #pragma unroll
        for (int m = 0; m < NZ - 1; m++)
            e[m + 1] = gidx((ql + (float)m + 0.5f) * s, xminf, invwf);
        #pragma unroll
        for (int m = 1; m < NZ; m++) if (e[m] < e[m - 1]) e[m] = e[m - 1];
        double num = 0.0;
        #pragma unroll
        for (int m = 0; m < NZ; m++) {
            u32 pc0 = g_pc[e[m]], pc1 = g_pc[e[m + 1]];
            u64 ps0 = g_ps[e[m]], ps1 = g_ps[e[m + 1]];
            double Nm = (double)(pc1 - pc0);
            double S1 = ((double)(s64)(ps1 - ps0) + Nm * cmind) * INVFIXS;
            float a = (ql + (float)m) * s;
            double ad = (double)a;
            num += ad * ad * Nm - 2.0 * ad * S1;
        }
        s_score[c] = num / (double)ntot;   // Σx² omitted: constant offset
    }
    __syncthreads();

    if (t < NITER) {
        int j = 0;
        double sm = s_score[t * NZ];
        #pragma unroll
        for (int z = 1; z < NZ; z++) {
            double s = s_score[t * NZ + z];
            if (s < sm) { sm = s; j = z; }   // first-occurrence argmin
        }
        sm_i[t] = sm; j_i[t] = j;
    }
    __syncthreads();
    if (t == 0) {
        double best = 1e30;
        float bmin = g_xminf;
        float bmax = g_xmaxf;
        for (int i = 0; i < NITER; i++) {
            if (sm_i[i] < best) {             // strict <, like reference
                best = sm_i[i];
                bmin = g_newmin[i * NZ + j_i[i]];
                bmax = g_newmax[i * NZ + j_i[i]];
            }
        }
        out[0] = bmin;
        out[1] = bmax;
    }
}

extern "C" void kernel_launch(void* const* d_in, const int* in_sizes, int n_in,
                              void* d_out, int out_size) {
    const float* x = (const float*)d_in[0];
    int n = in_sizes[0];
    int n4 = n / 4;

    minmax_clear_kernel<<<MMGRID, 256>>>((const float4*)x, n4);
    cand_kernel<<<1, 512>>>();
    hist_kernel<<<2048, 256>>>((const float4*)x, n4);
    chunkred_kernel<<<NCHUNK, 256>>>();
    binscan_kernel<<<NCHUNK, CHUNK>>>();
    finish_kernel<<<1, 1024>>>((float*)d_out, n);
}